// round 4
// baseline (speedup 1.0000x reference)
#include <cuda_runtime.h>

#define B_    8
#define N_    2048
#define FIN_  128
#define FOUT_ 64
#define TJ    128
#define WARPS 8

// Scratch (no allocations allowed)
__device__ float g_h [B_ * N_ * FOUT_];   // 4 MB
__device__ float g_s1[B_ * N_];
__device__ float g_s2[B_ * N_];

// packed fp32x2 FMA (Blackwell): d = a*b + d on two lanes
__device__ __forceinline__ void fma2(unsigned long long& d,
                                     unsigned long long a,
                                     unsigned long long b) {
    asm("fma.rn.f32x2 %0, %1, %2, %0;" : "+l"(d) : "l"(a), "l"(b));
}

// ---------------------------------------------------------------------------
// Kernel 1: h = x @ W   (+ fused s1 = h@a1, s2 = h@a2)
// block = 256 threads = 16 rows x 16 col-groups (4 cols each)
// ---------------------------------------------------------------------------
__global__ void __launch_bounds__(256)
gat_h_kernel(const float* __restrict__ x,
             const float* __restrict__ W,
             const float* __restrict__ a) {
    __shared__ float Wsm[FIN_ * FOUT_];   // 32 KB
    __shared__ float xsm[16 * FIN_];      // 8 KB

    const int tid  = threadIdx.x;
    const int row0 = blockIdx.x * 16;

    {   // load W (2048 float4)
        const float4* src = (const float4*)W;
        float4* dst = (float4*)Wsm;
#pragma unroll
        for (int i = 0; i < 8; i++) dst[tid + 256 * i] = src[tid + 256 * i];
    }
    {   // load 16 rows of x (512 float4)
        const float4* src = (const float4*)(x + (size_t)row0 * FIN_);
        float4* dst = (float4*)xsm;
#pragma unroll
        for (int i = 0; i < 2; i++) dst[tid + 256 * i] = src[tid + 256 * i];
    }
    __syncthreads();

    const int r  = tid >> 4;
    const int cg = tid & 15;

    float4 acc = make_float4(0.f, 0.f, 0.f, 0.f);
#pragma unroll 8
    for (int k = 0; k < FIN_; k++) {
        const float  xv = xsm[r * FIN_ + k];
        const float4 w4 = *(const float4*)(Wsm + k * FOUT_ + cg * 4);
        acc.x += xv * w4.x; acc.y += xv * w4.y;
        acc.z += xv * w4.z; acc.w += xv * w4.w;
    }

    const int row = row0 + r;
    *(float4*)(g_h + (size_t)row * FOUT_ + cg * 4) = acc;

    // fused s1/s2: dot with a1/a2, reduce across the 16 col-group lanes
    const float4 a1 = *(const float4*)(a + cg * 4);
    const float4 a2 = *(const float4*)(a + FOUT_ + cg * 4);
    float s1 = acc.x * a1.x + acc.y * a1.y + acc.z * a1.z + acc.w * a1.w;
    float s2 = acc.x * a2.x + acc.y * a2.y + acc.z * a2.z + acc.w * a2.w;
#pragma unroll
    for (int m = 8; m >= 1; m >>= 1) {
        s1 += __shfl_xor_sync(0xffffffffu, s1, m);
        s2 += __shfl_xor_sync(0xffffffffu, s2, m);
    }
    if (cg == 0) { g_s1[row] = s1; g_s2[row] = s2; }
}

// ---------------------------------------------------------------------------
// Kernel 2: fused  e -> mask -> softmax (no-max single pass) -> att@h -> LN -> ELU
// block = 256 threads (8 warps), each warp owns 8 i-rows, block owns 64 rows.
// j processed in tiles of TJ=128; h-tile shared in smem; per-warp p buffer
// stored as duplicated float2 {p,p} for the packed-fp32x2 FMA path.
// smem: h 32 KB + s2 0.5 KB + p 72 KB = 107008 B  -> 2 blocks/SM
// ---------------------------------------------------------------------------
__global__ void __launch_bounds__(256)
gat_attn_kernel(const int*   __restrict__ adj,
                const float* __restrict__ gamma,
                const float* __restrict__ beta,
                float*       __restrict__ out) {
    extern __shared__ float smem[];
    float*  hs  = smem;                       // [TJ][64]
    float*  s2s = hs + TJ * FOUT_;            // [TJ]
    float2* ps  = (float2*)(s2s + TJ);        // [WARPS][TJ*9] (pad 9: conflict-free)

    const int b    = blockIdx.y;
    const int row0 = blockIdx.x * 64;
    const int tid  = threadIdx.x;
    const int w    = tid >> 5;
    const int lane = tid & 31;
    const int rg   = lane >> 4;               // row-group (0/1): rows rg*4..rg*4+3
    const int cl   = lane & 15;               // col-group: cols cl*4..cl*4+3

    float2* pw = ps + w * (TJ * 9);
    const float* hB   = g_h + (size_t)b * N_ * FOUT_;
    const int*   adjB = adj + (size_t)b * N_ * N_;

    float s1r[8];
#pragma unroll
    for (int r = 0; r < 8; r++)
        s1r[r] = g_s1[b * N_ + row0 + w * 8 + r];

    unsigned long long acc[4][2];             // 4 rows x 4 cols as 2x f32x2 each
#pragma unroll
    for (int i = 0; i < 4; i++) { acc[i][0] = 0ull; acc[i][1] = 0ull; }
    float lsum[8];
#pragma unroll
    for (int r = 0; r < 8; r++) lsum[r] = 0.f;

    for (int j0 = 0; j0 < N_; j0 += TJ) {
        __syncthreads();                      // prior tile fully consumed
        {   // cooperative load of h tile (2048 float4) and s2 tile
            const float4* src = (const float4*)(hB + (size_t)j0 * FOUT_);
            float4* dst = (float4*)hs;
#pragma unroll
            for (int i = 0; i < 8; i++) dst[tid + 256 * i] = src[tid + 256 * i];
            if (tid < TJ) s2s[tid] = g_s2[b * N_ + j0 + tid];
        }
        __syncthreads();

        // ---- Phase A: p = adj ? exp(leakyrelu(s1+s2)) : 0, store {p,p} ----
#pragma unroll
        for (int k = 0; k < 4; k++) {
            const int   jj  = lane + 32 * k;
            const float s2v = s2s[jj];
            const int*  arow = adjB + j0 + jj;
#pragma unroll
            for (int r = 0; r < 8; r++) {
                const int row = row0 + w * 8 + r;
                const int av  = arow[(size_t)row * N_];
                float e = s1r[r] + s2v;
                e = fmaxf(e, 0.2f * e);                 // leaky_relu(., 0.2)
                float p = (av > 0) ? __expf(e) : 0.f;   // no-max softmax numerator
                lsum[r] += p;
                pw[jj * 9 + r] = make_float2(p, p);
            }
        }
        __syncwarp();

        // ---- Phase B: acc[r][c] += p[r][jj] * h[jj][c]  (packed f32x2) ----
#pragma unroll 8
        for (int jj = 0; jj < TJ; jj++) {
            const ulonglong2 hv =
                *(const ulonglong2*)(hs + jj * FOUT_ + cl * 4);
            const float2* pp = pw + jj * 9 + rg * 4;
#pragma unroll
            for (int ri = 0; ri < 4; ri++) {
                const unsigned long long pd =
                    *(const unsigned long long*)(pp + ri);
                fma2(acc[ri][0], hv.x, pd);
                fma2(acc[ri][1], hv.y, pd);
            }
        }
        __syncwarp();
    }

    // ---- Epilogue: divide by l, LayerNorm over 64 features, ELU, store ----
#pragma unroll
    for (int r = 0; r < 8; r++) {
        float v = lsum[r];
#pragma unroll
        for (int m = 16; m >= 1; m >>= 1)
            v += __shfl_xor_sync(0xffffffffu, v, m);
        lsum[r] = v;
    }

    const float4 g4  = *(const float4*)(gamma + cl * 4);
    const float4 be4 = *(const float4*)(beta + cl * 4);

#pragma unroll
    for (int ri = 0; ri < 4; ri++) {
        const int   r   = rg * 4 + ri;
        const float inv = 1.f / lsum[r];
        union U { unsigned long long u; float2 f; };
        U u0, u1; u0.u = acc[ri][0]; u1.u = acc[ri][1];
        float v0 = u0.f.x * inv, v1 = u0.f.y * inv;
        float v2 = u1.f.x * inv, v3 = u1.f.y * inv;

        float s = v0 + v1 + v2 + v3;
#pragma unroll
        for (int m = 8; m >= 1; m >>= 1)
            s += __shfl_xor_sync(0xffffffffu, s, m);
        const float mu = s * (1.0f / FOUT_);

        const float d0 = v0 - mu, d1 = v1 - mu, d2 = v2 - mu, d3 = v3 - mu;
        float q = d0 * d0 + d1 * d1 + d2 * d2 + d3 * d3;
#pragma unroll
        for (int m = 8; m >= 1; m >>= 1)
            q += __shfl_xor_sync(0xffffffffu, q, m);
        const float rstd = rsqrtf(q * (1.0f / FOUT_) + 1e-5f);

        const float y0 = d0 * rstd * g4.x + be4.x;
        const float y1 = d1 * rstd * g4.y + be4.y;
        const float y2 = d2 * rstd * g4.z + be4.z;
        const float y3 = d3 * rstd * g4.w + be4.w;

        float4 o;
        o.x = y0 > 0.f ? y0 : expm1f(y0);
        o.y = y1 > 0.f ? y1 : expm1f(y1);
        o.z = y2 > 0.f ? y2 : expm1f(y2);
        o.w = y3 > 0.f ? y3 : expm1f(y3);

        const int row = row0 + w * 8 + r;
        *(float4*)(out + ((size_t)b * N_ + row) * FOUT_ + cl * 4) = o;
    }
}

// ---------------------------------------------------------------------------
extern "C" void kernel_launch(void* const* d_in, const int* in_sizes, int n_in,
                              void* d_out, int out_size) {
    const float* x     = (const float*)d_in[0];
    const int*   adj   = (const int*)  d_in[1];
    const float* W     = (const float*)d_in[2];
    const float* a     = (const float*)d_in[3];
    const float* gamma = (const float*)d_in[4];
    const float* beta  = (const float*)d_in[5];
    float* out = (float*)d_out;

    gat_h_kernel<<<(B_ * N_) / 16, 256>>>(x, W, a);

    const int smem_bytes = (TJ * FOUT_ + TJ) * 4 + WARPS * TJ * 9 * 8; // 107008
    cudaFuncSetAttribute(gat_attn_kernel,
                         cudaFuncAttributeMaxDynamicSharedMemorySize, smem_bytes);
    gat_attn_kernel<<<dim3(N_ / 64, B_), 256, smem_bytes>>>(adj, gamma, beta, out);
}

// round 5
// speedup vs baseline: 1.2417x; 1.2417x over previous
#include <cuda_runtime.h>
#include <cstdint>

#define B_    8
#define N_    2048
#define FIN_  128
#define FOUT_ 64
#define TJ    64
#define NT    (N_ / TJ)      // 32 tiles
#define WARPS 8

// Scratch (no allocations allowed)
__device__ __align__(16) float g_h [B_ * N_ * FOUT_];   // 4 MB
__device__ __align__(16) float g_s1[B_ * N_];
__device__ __align__(16) float g_s2[B_ * N_];

// packed fp32x2 FMA (Blackwell): d += a*b on two lanes
__device__ __forceinline__ void fma2(unsigned long long& d,
                                     unsigned long long a,
                                     unsigned long long b) {
    asm("fma.rn.f32x2 %0, %1, %2, %0;" : "+l"(d) : "l"(a), "l"(b));
}

__device__ __forceinline__ void cp16(uint32_t s, const void* g) {
    asm volatile("cp.async.cg.shared.global [%0], [%1], 16;" :: "r"(s), "l"(g));
}
__device__ __forceinline__ void cp_commit() {
    asm volatile("cp.async.commit_group;" ::: "memory");
}
__device__ __forceinline__ void cp_wait1() {
    asm volatile("cp.async.wait_group 1;" ::: "memory");
}
__device__ __forceinline__ void cp_wait0() {
    asm volatile("cp.async.wait_group 0;" ::: "memory");
}

// ---------------------------------------------------------------------------
// Kernel 1: h = x @ W   (+ fused s1 = h@a1, s2 = h@a2)
// block = 256 threads; 32 rows/block; each thread computes 2 rows x 4 cols.
// ---------------------------------------------------------------------------
__global__ void __launch_bounds__(256)
gat_h_kernel(const float* __restrict__ x,
             const float* __restrict__ W,
             const float* __restrict__ a) {
    __shared__ float Wsm[FIN_ * FOUT_];   // 32 KB
    __shared__ float xsm[32 * FIN_];      // 16 KB

    const int tid  = threadIdx.x;
    const int row0 = blockIdx.x * 32;

    {   // load W (2048 float4)
        const float4* src = (const float4*)W;
        float4* dst = (float4*)Wsm;
#pragma unroll
        for (int i = 0; i < 8; i++) dst[tid + 256 * i] = src[tid + 256 * i];
    }
    {   // load 32 rows of x (1024 float4)
        const float4* src = (const float4*)(x + (size_t)row0 * FIN_);
        float4* dst = (float4*)xsm;
#pragma unroll
        for (int i = 0; i < 4; i++) dst[tid + 256 * i] = src[tid + 256 * i];
    }
    __syncthreads();

    const int r  = tid >> 4;      // 0..15
    const int cg = tid & 15;      // 0..15 (4 cols each)

    float4 acc0 = make_float4(0.f, 0.f, 0.f, 0.f);
    float4 acc1 = make_float4(0.f, 0.f, 0.f, 0.f);
#pragma unroll 8
    for (int k = 0; k < FIN_; k++) {
        const float4 w4 = *(const float4*)(Wsm + k * FOUT_ + cg * 4);
        const float  x0 = xsm[r * FIN_ + k];
        const float  x1 = xsm[(r + 16) * FIN_ + k];
        acc0.x += x0 * w4.x; acc0.y += x0 * w4.y;
        acc0.z += x0 * w4.z; acc0.w += x0 * w4.w;
        acc1.x += x1 * w4.x; acc1.y += x1 * w4.y;
        acc1.z += x1 * w4.z; acc1.w += x1 * w4.w;
    }

    const float4 a1 = *(const float4*)(a + cg * 4);
    const float4 a2 = *(const float4*)(a + FOUT_ + cg * 4);

#pragma unroll
    for (int half = 0; half < 2; half++) {
        const float4 acc = half ? acc1 : acc0;
        const int row = row0 + half * 16 + r;
        *(float4*)(g_h + (size_t)row * FOUT_ + cg * 4) = acc;

        float s1 = acc.x * a1.x + acc.y * a1.y + acc.z * a1.z + acc.w * a1.w;
        float s2 = acc.x * a2.x + acc.y * a2.y + acc.z * a2.z + acc.w * a2.w;
#pragma unroll
        for (int m = 8; m >= 1; m >>= 1) {
            s1 += __shfl_xor_sync(0xffffffffu, s1, m);
            s2 += __shfl_xor_sync(0xffffffffu, s2, m);
        }
        if (cg == 0) { g_s1[row] = s1; g_s2[row] = s2; }
    }
}

// ---------------------------------------------------------------------------
// Kernel 2: fused  e -> mask -> softmax (no-max single pass) -> att@h -> LN -> ELU
// block = 256 threads (8 warps), each warp owns 8 i-rows -> 64 rows/block.
// j in tiles of TJ=64; h-tile AND adj-tile double-buffered via cp.async so
// compute sees only smem. p stored duplicated {p,p} (pad 9 -> conflict-free
// STS.64) for the packed f32x2 FMA path.
// smem: h 2x16KB + adj 2x16KB + s2 2x256B + p 36KB = 100.5 KB -> 2 blocks/SM
// ---------------------------------------------------------------------------
__global__ void __launch_bounds__(256, 2)
gat_attn_kernel(const int*   __restrict__ adj,
                const float* __restrict__ gamma,
                const float* __restrict__ beta,
                float*       __restrict__ out) {
    extern __shared__ float smem[];
    float*  hs   = smem;                          // [2][TJ*64]
    int*    ajs  = (int*)(hs + 2 * TJ * FOUT_);   // [2][64*TJ]
    float*  s2s  = (float*)(ajs + 2 * 64 * TJ);   // [2][TJ]
    float2* ps   = (float2*)(s2s + 2 * TJ);       // [WARPS][TJ*9]

    const int b    = blockIdx.y;
    const int row0 = blockIdx.x * 64;
    const int tid  = threadIdx.x;
    const int w    = tid >> 5;
    const int lane = tid & 31;
    const int rg   = lane >> 4;                   // 0/1
    const int cl   = lane & 15;                   // feature group

    float2* pw = ps + w * (TJ * 9);
    const float* hB   = g_h + (size_t)b * N_ * FOUT_;
    const int*   adjB = adj + (size_t)b * N_ * N_;

    float s1r[8];
#pragma unroll
    for (int r = 0; r < 8; r++)
        s1r[r] = g_s1[b * N_ + row0 + w * 8 + r];

    unsigned long long acc[4][2];
#pragma unroll
    for (int i = 0; i < 4; i++) { acc[i][0] = 0ull; acc[i][1] = 0ull; }
    float lsum[8];
#pragma unroll
    for (int r = 0; r < 8; r++) lsum[r] = 0.f;

    // ---- tile prefetch: h (16KB) + adj (16KB) + s2 (256B) via cp.async ----
    auto prefetch = [&](int t, int buf) {
        float* hdst = hs + buf * (TJ * FOUT_);
        const float* hsrc = hB + (size_t)t * TJ * FOUT_;
#pragma unroll
        for (int i = 0; i < 4; i++) {
            const int c = tid + 256 * i;      // 16B chunk id (1024 total)
            cp16((uint32_t)__cvta_generic_to_shared(hdst + c * 4), hsrc + c * 4);
        }
        int* adst = ajs + buf * (64 * TJ);
#pragma unroll
        for (int i = 0; i < 4; i++) {
            const int c  = tid + 256 * i;     // 1024 chunks of 4 ints
            const int rr = c >> 4;            // i-row within block (0..63)
            const int cc = (c & 15) * 4;      // j-col within tile
            cp16((uint32_t)__cvta_generic_to_shared(adst + rr * TJ + cc),
                 adjB + (size_t)(row0 + rr) * N_ + t * TJ + cc);
        }
        if (tid < TJ / 4)
            cp16((uint32_t)__cvta_generic_to_shared(s2s + buf * TJ + tid * 4),
                 g_s2 + b * N_ + t * TJ + tid * 4);
    };

    prefetch(0, 0);
    cp_commit();

    for (int t = 0; t < NT; t++) {
        __syncthreads();                       // everyone done with buf (t+1)&1
        if (t + 1 < NT) {
            prefetch(t + 1, (t + 1) & 1);
            cp_commit();
            cp_wait1();                        // tile t landed
        } else {
            cp_wait0();
        }
        __syncthreads();                       // tile t visible to all

        const int    buf = t & 1;
        const float* hst = hs  + buf * (TJ * FOUT_);
        const int*   ast = ajs + buf * (64 * TJ);
        const float* s2t = s2s + buf * TJ;

        // ---- Phase A: p = adj ? exp(leakyrelu(s1+s2)) : 0, store {p,p} ----
#pragma unroll
        for (int k = 0; k < 2; k++) {
            const int   jj  = lane + 32 * k;
            const float s2v = s2t[jj];
            const int*  ac  = ast + (w * 8) * TJ + jj;
#pragma unroll
            for (int r = 0; r < 8; r++) {
                const int av = ac[r * TJ];
                float e = s1r[r] + s2v;
                e = fmaxf(e, 0.2f * e);
                float p = (av > 0) ? __expf(e) : 0.f;
                lsum[r] += p;
                pw[jj * 9 + r] = make_float2(p, p);
            }
        }
        __syncwarp();

        // ---- Phase B: acc[r][c] += p[r][jj] * h[jj][c]  (packed f32x2) ----
#pragma unroll 8
        for (int jj = 0; jj < TJ; jj++) {
            const ulonglong2 hv =
                *(const ulonglong2*)(hst + jj * FOUT_ + cl * 4);
            const float2* pp = pw + jj * 9 + rg * 4;
#pragma unroll
            for (int ri = 0; ri < 4; ri++) {
                const unsigned long long pd =
                    *(const unsigned long long*)(pp + ri);
                fma2(acc[ri][0], hv.x, pd);
                fma2(acc[ri][1], hv.y, pd);
            }
        }
        __syncwarp();
    }

    // ---- Epilogue: divide by l, LayerNorm over 64 features, ELU, store ----
#pragma unroll
    for (int r = 0; r < 8; r++) {
        float v = lsum[r];
#pragma unroll
        for (int m = 16; m >= 1; m >>= 1)
            v += __shfl_xor_sync(0xffffffffu, v, m);
        lsum[r] = v;
    }

    const float4 g4  = *(const float4*)(gamma + cl * 4);
    const float4 be4 = *(const float4*)(beta + cl * 4);

#pragma unroll
    for (int ri = 0; ri < 4; ri++) {
        const int   r   = rg * 4 + ri;
        const float inv = 1.f / lsum[r];
        union U { unsigned long long u; float2 f; };
        U u0, u1; u0.u = acc[ri][0]; u1.u = acc[ri][1];
        float v0 = u0.f.x * inv, v1 = u0.f.y * inv;
        float v2 = u1.f.x * inv, v3 = u1.f.y * inv;

        float s = v0 + v1 + v2 + v3;
#pragma unroll
        for (int m = 8; m >= 1; m >>= 1)
            s += __shfl_xor_sync(0xffffffffu, s, m);
        const float mu = s * (1.0f / FOUT_);

        const float d0 = v0 - mu, d1 = v1 - mu, d2 = v2 - mu, d3 = v3 - mu;
        float q = d0 * d0 + d1 * d1 + d2 * d2 + d3 * d3;
#pragma unroll
        for (int m = 8; m >= 1; m >>= 1)
            q += __shfl_xor_sync(0xffffffffu, q, m);
        const float rstd = rsqrtf(q * (1.0f / FOUT_) + 1e-5f);

        const float y0 = d0 * rstd * g4.x + be4.x;
        const float y1 = d1 * rstd * g4.y + be4.y;
        const float y2 = d2 * rstd * g4.z + be4.z;
        const float y3 = d3 * rstd * g4.w + be4.w;

        float4 o;
        o.x = y0 > 0.f ? y0 : expm1f(y0);
        o.y = y1 > 0.f ? y1 : expm1f(y1);
        o.z = y2 > 0.f ? y2 : expm1f(y2);
        o.w = y3 > 0.f ? y3 : expm1f(y3);

        const int row = row0 + w * 8 + r;
        *(float4*)(out + ((size_t)b * N_ + row) * FOUT_ + cl * 4) = o;
    }
}

// ---------------------------------------------------------------------------
extern "C" void kernel_launch(void* const* d_in, const int* in_sizes, int n_in,
                              void* d_out, int out_size) {
    const float* x     = (const float*)d_in[0];
    const int*   adj   = (const int*)  d_in[1];
    const float* W     = (const float*)d_in[2];
    const float* a     = (const float*)d_in[3];
    const float* gamma = (const float*)d_in[4];
    const float* beta  = (const float*)d_in[5];
    float* out = (float*)d_out;

    gat_h_kernel<<<(B_ * N_) / 32, 256>>>(x, W, a);

    const int smem_bytes = 2 * TJ * FOUT_ * 4      // h double buffer
                         + 2 * 64 * TJ * 4         // adj double buffer
                         + 2 * TJ * 4              // s2 double buffer
                         + WARPS * TJ * 9 * 8;     // p buffers
    cudaFuncSetAttribute(gat_attn_kernel,
                         cudaFuncAttributeMaxDynamicSharedMemorySize, smem_bytes);
    gat_attn_kernel<<<dim3(N_ / 64, B_), 256, smem_bytes>>>(adj, gamma, beta, out);
}

// round 8
// speedup vs baseline: 2.0806x; 1.6756x over previous
#include <cuda_runtime.h>
#include <cuda_bf16.h>
#include <cstdint>

#define B_    8
#define N_    2048
#define FIN_  128
#define FOUT_ 64
#define TJ    64
#define NT    (N_ / TJ)      // 32 tiles
#define MR    128            // i-rows per CTA

// ---------------- global scratch (no allocations allowed) ----------------
__device__ __align__(16) float         g_s1[B_ * N_];
__device__ __align__(16) float         g_s2[B_ * N_];
__device__ __align__(16) __nv_bfloat16 g_hT_hi[B_ * FOUT_ * N_];  // [b][f][n]
__device__ __align__(16) __nv_bfloat16 g_hT_lo[B_ * FOUT_ * N_];

// ---------------- helpers ----------------
__device__ __forceinline__ uint32_t pack_bf16(float a, float b) {
    __nv_bfloat162 t = __float22bfloat162_rn(make_float2(a, b));
    return *reinterpret_cast<uint32_t*>(&t);
}
__device__ __forceinline__ void cp16(uint32_t s, const void* g) {
    asm volatile("cp.async.cg.shared.global [%0], [%1], 16;" :: "r"(s), "l"(g));
}
__device__ __forceinline__ void cp_commit() {
    asm volatile("cp.async.commit_group;" ::: "memory");
}
__device__ __forceinline__ void cp_wait1() {
    asm volatile("cp.async.wait_group 1;" ::: "memory");
}
__device__ __forceinline__ void cp_wait0() {
    asm volatile("cp.async.wait_group 0;" ::: "memory");
}
__device__ __forceinline__ uint32_t smem_u32(const void* p) {
    uint32_t a;
    asm("{ .reg .u64 t; cvta.to.shared.u64 t, %1; cvt.u32.u64 %0, t; }" : "=r"(a) : "l"(p));
    return a;
}
// m16n8k16 bf16 MMA, fp32 accumulate in place
__device__ __forceinline__ void mma16816(float* d, const uint32_t* a,
                                         uint32_t b0, uint32_t b1) {
    asm volatile(
        "mma.sync.aligned.m16n8k16.row.col.f32.bf16.bf16.f32 "
        "{%0,%1,%2,%3}, {%4,%5,%6,%7}, {%8,%9}, {%0,%1,%2,%3};"
        : "+f"(d[0]), "+f"(d[1]), "+f"(d[2]), "+f"(d[3])
        : "r"(a[0]), "r"(a[1]), "r"(a[2]), "r"(a[3]), "r"(b0), "r"(b1));
}
__device__ __forceinline__ float pv(int av, float e) {
    e = fmaxf(e, 0.2f * e);                  // leaky_relu(., 0.2)
    return (av > 0) ? __expf(e) : 0.f;       // no-max softmax numerator
}

// ---------------------------------------------------------------------------
// Kernel 1: h = x@W -> hT_hi/hT_lo (bf16, [b][f][n]) + s1 = h@a1, s2 = h@a2
// ---------------------------------------------------------------------------
__global__ void __launch_bounds__(256)
gat_h_kernel(const float* __restrict__ x,
             const float* __restrict__ W,
             const float* __restrict__ a) {
    extern __shared__ float sm1[];
    float* Wsm = sm1;            // [128*64]
    float* xsm = sm1 + 8192;     // [32*128]
    float* hsm = xsm;            // reuse: [32][69]

    const int tid   = threadIdx.x;
    const int row0g = blockIdx.x * 32;
    const int b     = row0g >> 11;
    const int n0    = row0g & (N_ - 1);

    {
        const float4* src = (const float4*)W;
        float4* dst = (float4*)Wsm;
#pragma unroll
        for (int i = 0; i < 8; i++) dst[tid + 256 * i] = src[tid + 256 * i];
    }
    {
        const float4* src = (const float4*)(x + (size_t)row0g * FIN_);
        float4* dst = (float4*)xsm;
#pragma unroll
        for (int i = 0; i < 4; i++) dst[tid + 256 * i] = src[tid + 256 * i];
    }
    __syncthreads();

    const int r  = tid >> 4;
    const int cg = tid & 15;

    float4 acc0 = make_float4(0.f, 0.f, 0.f, 0.f);
    float4 acc1 = make_float4(0.f, 0.f, 0.f, 0.f);
#pragma unroll 8
    for (int k = 0; k < FIN_; k++) {
        const float4 w4 = *(const float4*)(Wsm + k * FOUT_ + cg * 4);
        const float  x0 = xsm[r * FIN_ + k];
        const float  x1 = xsm[(r + 16) * FIN_ + k];
        acc0.x += x0 * w4.x; acc0.y += x0 * w4.y;
        acc0.z += x0 * w4.z; acc0.w += x0 * w4.w;
        acc1.x += x1 * w4.x; acc1.y += x1 * w4.y;
        acc1.z += x1 * w4.z; acc1.w += x1 * w4.w;
    }

    const float4 a1 = *(const float4*)(a + cg * 4);
    const float4 a2 = *(const float4*)(a + FOUT_ + cg * 4);
#pragma unroll
    for (int half = 0; half < 2; half++) {
        const float4 acc = half ? acc1 : acc0;
        const int row = row0g + half * 16 + r;
        float s1 = acc.x * a1.x + acc.y * a1.y + acc.z * a1.z + acc.w * a1.w;
        float s2 = acc.x * a2.x + acc.y * a2.y + acc.z * a2.z + acc.w * a2.w;
#pragma unroll
        for (int m = 8; m >= 1; m >>= 1) {
            s1 += __shfl_xor_sync(0xffffffffu, s1, m);
            s2 += __shfl_xor_sync(0xffffffffu, s2, m);
        }
        if (cg == 0) { g_s1[row] = s1; g_s2[row] = s2; }
    }

    __syncthreads();     // xsm reads done; reuse as hsm
    hsm[r * 69 + cg * 4 + 0] = acc0.x;  hsm[r * 69 + cg * 4 + 1] = acc0.y;
    hsm[r * 69 + cg * 4 + 2] = acc0.z;  hsm[r * 69 + cg * 4 + 3] = acc0.w;
    hsm[(r + 16) * 69 + cg * 4 + 0] = acc1.x;  hsm[(r + 16) * 69 + cg * 4 + 1] = acc1.y;
    hsm[(r + 16) * 69 + cg * 4 + 2] = acc1.z;  hsm[(r + 16) * 69 + cg * 4 + 3] = acc1.w;
    __syncthreads();

    // transpose + hi/lo bf16 split: thread -> (f = tid>>2, 8 consecutive n)
    const int f  = tid >> 2;
    const int jq = tid & 3;
    float v[8];
#pragma unroll
    for (int u = 0; u < 8; u++) v[u] = hsm[(jq * 8 + u) * 69 + f];

    uint4 hiv, lov;
    uint32_t* hp = (uint32_t*)&hiv;
    uint32_t* lp = (uint32_t*)&lov;
#pragma unroll
    for (int q = 0; q < 4; q++) {
        const float va = v[2 * q], vb = v[2 * q + 1];
        const uint32_t ph = pack_bf16(va, vb);
        const __nv_bfloat162 pb = *reinterpret_cast<const __nv_bfloat162*>(&ph);
        hp[q] = ph;
        lp[q] = pack_bf16(va - __low2float(pb), vb - __high2float(pb));
    }
    const size_t o = ((size_t)(b * FOUT_ + f)) * N_ + n0 + jq * 8;
    *(uint4*)(g_hT_hi + o) = hiv;
    *(uint4*)(g_hT_lo + o) = lov;
}

// ---------------------------------------------------------------------------
// Kernel 2: fused mask/softmax (no-max) -> HMMA hi/lo P·V -> LN -> ELU
// 256 threads = 8 warps x 16 i-rows = 128 rows/CTA; grid (16, 8).
// smem offsets (bytes):
#define ADJ_OFF  0u          // adj  [2][128][68] int   (69632)
#define HH_OFF   69632u      // hT_hi [2][64][72] bf16  (18432; row stride 144B)
#define HL_OFF   88064u      // hT_lo                    (18432)
#define S2_OFF   106496u     // s2   [2][64] f32         (512)
#define GB_OFF   107008u     // gamma[64] + beta[64]     (512)
#define SMEM2    107520u
// ---------------------------------------------------------------------------
__global__ void __launch_bounds__(256, 2)
gat_attn_kernel(const int*   __restrict__ adj,
                const float* __restrict__ gamma,
                const float* __restrict__ beta,
                float*       __restrict__ out) {
    extern __shared__ char smem[];
    const uint32_t sb = smem_u32(smem);

    const int b    = blockIdx.y;
    const int row0 = blockIdx.x * MR;
    const int tid  = threadIdx.x;
    const int w    = tid >> 5;
    const int lane = tid & 31;
    const int g    = lane >> 2;                 // 0..7 (row in frag)
    const int qt   = lane & 3;                  // 0..3 (k group in frag)

    const int* adjB = adj + (size_t)b * N_ * N_;

    auto prefetch = [&](int t) {
        const uint32_t ad = sb + ADJ_OFF + (uint32_t)(t & 1) * 34816u;
#pragma unroll
        for (int k = 0; k < 8; k++) {
            const int c  = tid + 256 * k;       // 2048 chunks of 16B
            const int rr = c >> 4, cc = c & 15;
            cp16(ad + rr * 272 + cc * 16,
                 adjB + (size_t)(row0 + rr) * N_ + t * TJ + cc * 4);
        }
        const uint32_t hb = (uint32_t)(t & 1) * 9216u;
#pragma unroll
        for (int k = 0; k < 2; k++) {
            const int c = tid + 256 * k;        // 512 chunks of 16B
            const int f = c >> 3, jc = c & 7;
            const size_t go = ((size_t)(b * FOUT_ + f)) * N_ + t * TJ + jc * 8;
            const uint32_t so = (uint32_t)(f * 144 + jc * 16);
            cp16(sb + HH_OFF + hb + so, g_hT_hi + go);
            cp16(sb + HL_OFF + hb + so, g_hT_lo + go);
        }
        if (tid < 16)
            cp16(sb + S2_OFF + (uint32_t)(t & 1) * 256u + tid * 16,
                 g_s2 + b * N_ + t * TJ + tid * 4);
    };

    prefetch(0);
    cp_commit();

    // gamma/beta to smem
    if (tid < 64) {
        ((float*)(smem + GB_OFF))[tid]      = gamma[tid];
        ((float*)(smem + GB_OFF))[64 + tid] = beta[tid];
    }

    const int i0 = w * 16 + g;          // local row
    const int i1 = i0 + 8;
    const float s10 = g_s1[b * N_ + row0 + i0];
    const float s11 = g_s1[b * N_ + row0 + i1];

    float accs[8][4];
#pragma unroll
    for (int nc = 0; nc < 8; nc++)
#pragma unroll
        for (int q = 0; q < 4; q++) accs[nc][q] = 0.f;
    float l0 = 0.f, l1 = 0.f;

    for (int t = 0; t < NT; t++) {
        if (t + 1 < NT) { prefetch(t + 1); cp_commit(); cp_wait1(); }
        else            { cp_wait0(); }
        __syncthreads();                         // tile t visible everywhere

        const int*   adjt = (const int*)  (smem + ADJ_OFF + (t & 1) * 34816);
        const float* s2t  = (const float*)(smem + S2_OFF  + (t & 1) * 256);
        const char*  hh   = smem + HH_OFF + (t & 1) * 9216;
        const char*  hl   = smem + HL_OFF + (t & 1) * 9216;

        // ---- Phase A: p straight into A-fragment registers (hi + lo) ----
        uint32_t aH[16], aL[16];
#pragma unroll
        for (int kc = 0; kc < 4; kc++) {
            const int jb = kc * 16 + 2 * qt;
            const float2 s2a = *(const float2*)(s2t + jb);
            const float2 s2b = *(const float2*)(s2t + jb + 8);
            const int2 A00 = *(const int2*)(adjt + i0 * 68 + jb);
            const int2 A08 = *(const int2*)(adjt + i0 * 68 + jb + 8);
            const int2 A10 = *(const int2*)(adjt + i1 * 68 + jb);
            const int2 A18 = *(const int2*)(adjt + i1 * 68 + jb + 8);

            const float p00 = pv(A00.x, s10 + s2a.x);
            const float p01 = pv(A00.y, s10 + s2a.y);
            const float p02 = pv(A08.x, s10 + s2b.x);
            const float p03 = pv(A08.y, s10 + s2b.y);
            const float p10 = pv(A10.x, s11 + s2a.x);
            const float p11 = pv(A10.y, s11 + s2a.y);
            const float p12 = pv(A18.x, s11 + s2b.x);
            const float p13 = pv(A18.y, s11 + s2b.y);

            l0 += (p00 + p01) + (p02 + p03);
            l1 += (p10 + p11) + (p12 + p13);

            // a0: row g k,k+1 | a1: row g+8 | a2: row g k+8,k+9 | a3: row g+8
            uint32_t h0 = pack_bf16(p00, p01);
            uint32_t h1 = pack_bf16(p10, p11);
            uint32_t h2 = pack_bf16(p02, p03);
            uint32_t h3 = pack_bf16(p12, p13);
            aH[kc * 4 + 0] = h0; aH[kc * 4 + 1] = h1;
            aH[kc * 4 + 2] = h2; aH[kc * 4 + 3] = h3;
            const __nv_bfloat162 b0 = *reinterpret_cast<const __nv_bfloat162*>(&h0);
            const __nv_bfloat162 b1 = *reinterpret_cast<const __nv_bfloat162*>(&h1);
            const __nv_bfloat162 b2 = *reinterpret_cast<const __nv_bfloat162*>(&h2);
            const __nv_bfloat162 b3 = *reinterpret_cast<const __nv_bfloat162*>(&h3);
            aL[kc * 4 + 0] = pack_bf16(p00 - __low2float(b0), p01 - __high2float(b0));
            aL[kc * 4 + 1] = pack_bf16(p10 - __low2float(b1), p11 - __high2float(b1));
            aL[kc * 4 + 2] = pack_bf16(p02 - __low2float(b2), p03 - __high2float(b2));
            aL[kc * 4 + 3] = pack_bf16(p12 - __low2float(b3), p13 - __high2float(b3));
        }

        // ---- Phase B: D += P_hi·H_hi + P_lo·H_hi + P_hi·H_lo (HMMA) ----
#pragma unroll
        for (int nc = 0; nc < 8; nc++) {
            const int n = nc * 8 + g;           // B col (feature)
            const char* rH = hh + n * 144 + qt * 4;
            const char* rL = hl + n * 144 + qt * 4;
#pragma unroll
            for (int kc = 0; kc < 4; kc++) {
                const uint32_t bh0 = *(const uint32_t*)(rH + kc * 32);
                const uint32_t bh1 = *(const uint32_t*)(rH + kc * 32 + 16);
                const uint32_t bl0 = *(const uint32_t*)(rL + kc * 32);
                const uint32_t bl1 = *(const uint32_t*)(rL + kc * 32 + 16);
                mma16816(accs[nc], aH + kc * 4, bh0, bh1);
                mma16816(accs[nc], aL + kc * 4, bh0, bh1);
                mma16816(accs[nc], aH + kc * 4, bl0, bl1);
            }
        }
        __syncthreads();                         // done with buf t&1
    }

    // ---- softmax denominators (quad reduce: lanes sharing g) ----
    l0 += __shfl_xor_sync(0xffffffffu, l0, 1);
    l0 += __shfl_xor_sync(0xffffffffu, l0, 2);
    l1 += __shfl_xor_sync(0xffffffffu, l1, 1);
    l1 += __shfl_xor_sync(0xffffffffu, l1, 2);
    const float inv0 = 1.f / l0;
    const float inv1 = 1.f / l1;

    const float* gsm = (const float*)(smem + GB_OFF);
    const float* bsm = gsm + 64;

    // ---- LayerNorm + ELU + store, per owned row ----
#pragma unroll
    for (int half = 0; half < 2; half++) {
        const float inv = half ? inv1 : inv0;
        const int   row = row0 + (half ? i1 : i0);
        float v[16];
        float s = 0.f;
#pragma unroll
        for (int nc = 0; nc < 8; nc++) {
            v[2 * nc + 0] = accs[nc][half * 2 + 0] * inv;
            v[2 * nc + 1] = accs[nc][half * 2 + 1] * inv;
            s += v[2 * nc] + v[2 * nc + 1];
        }
        s += __shfl_xor_sync(0xffffffffu, s, 1);
        s += __shfl_xor_sync(0xffffffffu, s, 2);
        const float mu = s * (1.0f / FOUT_);
        float q = 0.f;
#pragma unroll
        for (int c = 0; c < 16; c++) { const float d = v[c] - mu; q += d * d; }
        q += __shfl_xor_sync(0xffffffffu, q, 1);
        q += __shfl_xor_sync(0xffffffffu, q, 2);
        const float rstd = rsqrtf(q * (1.0f / FOUT_) + 1e-5f);

        float* op = out + ((size_t)b * N_ + row) * FOUT_;
#pragma unroll
        for (int nc = 0; nc < 8; nc++) {
            const int col = nc * 8 + 2 * qt;
            const float y0 = (v[2 * nc + 0] - mu) * rstd * gsm[col]     + bsm[col];
            const float y1 = (v[2 * nc + 1] - mu) * rstd * gsm[col + 1] + bsm[col + 1];
            float2 o;
            o.x = y0 > 0.f ? y0 : expm1f(y0);
            o.y = y1 > 0.f ? y1 : expm1f(y1);
            *(float2*)(op + col) = o;
        }
    }
}

// ---------------------------------------------------------------------------
extern "C" void kernel_launch(void* const* d_in, const int* in_sizes, int n_in,
                              void* d_out, int out_size) {
    const float* x     = (const float*)d_in[0];
    const int*   adj   = (const int*)  d_in[1];
    const float* W     = (const float*)d_in[2];
    const float* a     = (const float*)d_in[3];
    const float* gamma = (const float*)d_in[4];
    const float* beta  = (const float*)d_in[5];
    float* out = (float*)d_out;

    cudaFuncSetAttribute(gat_h_kernel,
                         cudaFuncAttributeMaxDynamicSharedMemorySize, 49152);
    cudaFuncSetAttribute(gat_attn_kernel,
                         cudaFuncAttributeMaxDynamicSharedMemorySize, SMEM2);

    gat_h_kernel<<<(B_ * N_) / 32, 256, 49152>>>(x, W, a);
    gat_attn_kernel<<<dim3(N_ / MR, B_), 256, SMEM2>>>(adj, gamma, beta, out);
}

// round 9
// speedup vs baseline: 2.7744x; 1.3335x over previous
#include <cuda_runtime.h>
#include <cuda_bf16.h>
#include <cstdint>

#define B_    8
#define N_    2048
#define FIN_  128
#define FOUT_ 64
#define TJ    64
#define NT    (N_ / TJ)      // 32 tiles
#define NSPL  2              // j-splits
#define NTS   (NT / NSPL)    // 16 tiles per split
#define MR    128            // i-rows per CTA

// ---------------- global scratch (no allocations allowed) ----------------
__device__ __align__(16) float         g_s1[B_ * N_];
__device__ __align__(16) float         g_s2[B_ * N_];
__device__ __align__(16) __nv_bfloat16 g_hT_hi[B_ * FOUT_ * N_];  // [b][f][n]
__device__ __align__(16) __nv_bfloat16 g_hT_lo[B_ * FOUT_ * N_];
__device__ __align__(16) float         g_pd[NSPL * B_ * N_ * FOUT_]; // partial D (8MB)
__device__ __align__(16) float         g_pl[NSPL * B_ * N_];         // partial l

// ---------------- helpers ----------------
__device__ __forceinline__ uint32_t pack_bf16(float a, float b) {
    __nv_bfloat162 t = __float22bfloat162_rn(make_float2(a, b));
    return *reinterpret_cast<uint32_t*>(&t);
}
__device__ __forceinline__ void cp16(uint32_t s, const void* g) {
    asm volatile("cp.async.cg.shared.global [%0], [%1], 16;" :: "r"(s), "l"(g));
}
__device__ __forceinline__ void cp_commit() {
    asm volatile("cp.async.commit_group;" ::: "memory");
}
__device__ __forceinline__ void cp_wait1() {
    asm volatile("cp.async.wait_group 1;" ::: "memory");
}
__device__ __forceinline__ void cp_wait0() {
    asm volatile("cp.async.wait_group 0;" ::: "memory");
}
__device__ __forceinline__ uint32_t smem_u32(const void* p) {
    uint32_t a;
    asm("{ .reg .u64 t; cvta.to.shared.u64 t, %1; cvt.u32.u64 %0, t; }" : "=r"(a) : "l"(p));
    return a;
}
// m16n8k16 bf16 MMA, fp32 accumulate in place
__device__ __forceinline__ void mma16816(float* d, const uint32_t* a,
                                         uint32_t b0, uint32_t b1) {
    asm volatile(
        "mma.sync.aligned.m16n8k16.row.col.f32.bf16.bf16.f32 "
        "{%0,%1,%2,%3}, {%4,%5,%6,%7}, {%8,%9}, {%0,%1,%2,%3};"
        : "+f"(d[0]), "+f"(d[1]), "+f"(d[2]), "+f"(d[3])
        : "r"(a[0]), "r"(a[1]), "r"(a[2]), "r"(a[3]), "r"(b0), "r"(b1));
}
__device__ __forceinline__ float pv(int av, float e) {
    e = fmaxf(e, 0.2f * e);                  // leaky_relu(., 0.2)
    return (av > 0) ? __expf(e) : 0.f;       // no-max softmax numerator
}

// ---------------------------------------------------------------------------
// Kernel 1: h = x@W -> hT_hi/hT_lo (bf16, [b][f][n]) + s1 = h@a1, s2 = h@a2
// 256 threads, 64 rows/block (W-load amortized over 64 rows).
// ---------------------------------------------------------------------------
__global__ void __launch_bounds__(256)
gat_h_kernel(const float* __restrict__ x,
             const float* __restrict__ W,
             const float* __restrict__ a) {
    extern __shared__ float sm1[];
    float* Wsm = sm1;            // [128*64]  32KB
    float* xsm = sm1 + 8192;     // [64*128]  32KB
    float* hsm = xsm;            // reuse: [64][69] (17.7KB)

    const int tid   = threadIdx.x;
    const int row0g = blockIdx.x * 64;
    const int b     = row0g >> 11;
    const int n0    = row0g & (N_ - 1);

    {
        const float4* src = (const float4*)W;
        float4* dst = (float4*)Wsm;
#pragma unroll
        for (int i = 0; i < 8; i++) dst[tid + 256 * i] = src[tid + 256 * i];
    }
    {
        const float4* src = (const float4*)(x + (size_t)row0g * FIN_);
        float4* dst = (float4*)xsm;
#pragma unroll
        for (int i = 0; i < 8; i++) dst[tid + 256 * i] = src[tid + 256 * i];
    }
    __syncthreads();

    const int r  = tid >> 4;      // 0..15
    const int cg = tid & 15;

    float4 acc[4];
#pragma unroll
    for (int q = 0; q < 4; q++) acc[q] = make_float4(0.f, 0.f, 0.f, 0.f);
#pragma unroll 4
    for (int k = 0; k < FIN_; k++) {
        const float4 w4 = *(const float4*)(Wsm + k * FOUT_ + cg * 4);
#pragma unroll
        for (int q = 0; q < 4; q++) {
            const float xv = xsm[(r + 16 * q) * FIN_ + k];
            acc[q].x += xv * w4.x; acc[q].y += xv * w4.y;
            acc[q].z += xv * w4.z; acc[q].w += xv * w4.w;
        }
    }

    const float4 a1 = *(const float4*)(a + cg * 4);
    const float4 a2 = *(const float4*)(a + FOUT_ + cg * 4);
#pragma unroll
    for (int q = 0; q < 4; q++) {
        const int row = row0g + 16 * q + r;
        float s1 = acc[q].x * a1.x + acc[q].y * a1.y + acc[q].z * a1.z + acc[q].w * a1.w;
        float s2 = acc[q].x * a2.x + acc[q].y * a2.y + acc[q].z * a2.z + acc[q].w * a2.w;
#pragma unroll
        for (int m = 8; m >= 1; m >>= 1) {
            s1 += __shfl_xor_sync(0xffffffffu, s1, m);
            s2 += __shfl_xor_sync(0xffffffffu, s2, m);
        }
        if (cg == 0) { g_s1[row] = s1; g_s2[row] = s2; }
    }

    __syncthreads();     // xsm reads done; reuse as hsm [64][69]
#pragma unroll
    for (int q = 0; q < 4; q++) {
        float* hp = hsm + (16 * q + r) * 69 + cg * 4;
        hp[0] = acc[q].x; hp[1] = acc[q].y; hp[2] = acc[q].z; hp[3] = acc[q].w;
    }
    __syncthreads();

    // transpose + hi/lo bf16 split: thread -> (f = tid>>2, 2 passes of 8 n)
    const int f  = tid >> 2;      // 0..63
    const int jq = tid & 3;
#pragma unroll
    for (int pass = 0; pass < 2; pass++) {
        const int nb = pass * 32 + jq * 8;
        float v[8];
#pragma unroll
        for (int u = 0; u < 8; u++) v[u] = hsm[(nb + u) * 69 + f];

        uint4 hiv, lov;
        uint32_t* hp = (uint32_t*)&hiv;
        uint32_t* lp = (uint32_t*)&lov;
#pragma unroll
        for (int q = 0; q < 4; q++) {
            const float va = v[2 * q], vb = v[2 * q + 1];
            const uint32_t ph = pack_bf16(va, vb);
            const __nv_bfloat162 pb = *reinterpret_cast<const __nv_bfloat162*>(&ph);
            hp[q] = ph;
            lp[q] = pack_bf16(va - __low2float(pb), vb - __high2float(pb));
        }
        const size_t o = ((size_t)(b * FOUT_ + f)) * N_ + n0 + nb;
        *(uint4*)(g_hT_hi + o) = hiv;
        *(uint4*)(g_hT_lo + o) = lov;
    }
}

// ---------------------------------------------------------------------------
// Kernel 2: fused mask/softmax (no-max) -> HMMA hi/lo P·V, j-split partials
// 256 threads = 8 warps x 16 i-rows = 128 rows/CTA; grid (16, 8, 2).
// smem offsets (bytes):
#define ADJ_OFF  0u          // adj  [2][128][68] int   (69632)
#define HH_OFF   69632u      // hT_hi [2][64][72] bf16  (18432; row stride 144B)
#define HL_OFF   88064u      // hT_lo                    (18432)
#define S2_OFF   106496u     // s2   [2][64] f32         (512)
#define SMEM2    107008u
// ---------------------------------------------------------------------------
__global__ void __launch_bounds__(256, 2)
gat_attn_kernel(const int* __restrict__ adj) {
    extern __shared__ char smem[];
    const uint32_t sb = smem_u32(smem);

    const int b    = blockIdx.y;
    const int row0 = blockIdx.x * MR;
    const int js   = blockIdx.z;
    const int t0   = js * NTS;
    const int tid  = threadIdx.x;
    const int w    = tid >> 5;
    const int lane = tid & 31;
    const int g    = lane >> 2;                 // 0..7 (row in frag)
    const int qt   = lane & 3;                  // 0..3 (k group in frag)

    const int* adjB = adj + (size_t)b * N_ * N_;

    auto prefetch = [&](int t, int buf) {
        const uint32_t ad = sb + ADJ_OFF + (uint32_t)buf * 34816u;
#pragma unroll
        for (int k = 0; k < 8; k++) {
            const int c  = tid + 256 * k;       // 2048 chunks of 16B
            const int rr = c >> 4, cc = c & 15;
            cp16(ad + rr * 272 + cc * 16,
                 adjB + (size_t)(row0 + rr) * N_ + t * TJ + cc * 4);
        }
        const uint32_t hb = (uint32_t)buf * 9216u;
#pragma unroll
        for (int k = 0; k < 2; k++) {
            const int c = tid + 256 * k;        // 512 chunks of 16B
            const int f = c >> 3, jc = c & 7;
            const size_t go = ((size_t)(b * FOUT_ + f)) * N_ + t * TJ + jc * 8;
            const uint32_t so = (uint32_t)(f * 144 + jc * 16);
            cp16(sb + HH_OFF + hb + so, g_hT_hi + go);
            cp16(sb + HL_OFF + hb + so, g_hT_lo + go);
        }
        if (tid < 16)
            cp16(sb + S2_OFF + (uint32_t)buf * 256u + tid * 16,
                 g_s2 + b * N_ + t * TJ + tid * 4);
    };

    prefetch(t0, 0);
    cp_commit();

    const int i0 = w * 16 + g;          // local row
    const int i1 = i0 + 8;
    const float s10 = g_s1[b * N_ + row0 + i0];
    const float s11 = g_s1[b * N_ + row0 + i1];

    float accs[8][4];
#pragma unroll
    for (int nc = 0; nc < 8; nc++)
#pragma unroll
        for (int q = 0; q < 4; q++) accs[nc][q] = 0.f;
    float l0 = 0.f, l1 = 0.f;

    for (int tt = 0; tt < NTS; tt++) {
        if (tt + 1 < NTS) { prefetch(t0 + tt + 1, (tt + 1) & 1); cp_commit(); cp_wait1(); }
        else              { cp_wait0(); }
        __syncthreads();                         // tile tt visible everywhere

        const int*   adjt = (const int*)  (smem + ADJ_OFF + (tt & 1) * 34816);
        const float* s2t  = (const float*)(smem + S2_OFF  + (tt & 1) * 256);
        const char*  hh   = smem + HH_OFF + (tt & 1) * 9216;
        const char*  hl   = smem + HL_OFF + (tt & 1) * 9216;

        // ---- Phase A: p straight into A-fragment registers (hi + lo) ----
        uint32_t aH[16], aL[16];
#pragma unroll
        for (int kc = 0; kc < 4; kc++) {
            const int jb = kc * 16 + 2 * qt;
            const float2 s2a = *(const float2*)(s2t + jb);
            const float2 s2b = *(const float2*)(s2t + jb + 8);
            const int2 A00 = *(const int2*)(adjt + i0 * 68 + jb);
            const int2 A08 = *(const int2*)(adjt + i0 * 68 + jb + 8);
            const int2 A10 = *(const int2*)(adjt + i1 * 68 + jb);
            const int2 A18 = *(const int2*)(adjt + i1 * 68 + jb + 8);

            const float p00 = pv(A00.x, s10 + s2a.x);
            const float p01 = pv(A00.y, s10 + s2a.y);
            const float p02 = pv(A08.x, s10 + s2b.x);
            const float p03 = pv(A08.y, s10 + s2b.y);
            const float p10 = pv(A10.x, s11 + s2a.x);
            const float p11 = pv(A10.y, s11 + s2a.y);
            const float p12 = pv(A18.x, s11 + s2b.x);
            const float p13 = pv(A18.y, s11 + s2b.y);

            l0 += (p00 + p01) + (p02 + p03);
            l1 += (p10 + p11) + (p12 + p13);

            uint32_t h0 = pack_bf16(p00, p01);
            uint32_t h1 = pack_bf16(p10, p11);
            uint32_t h2 = pack_bf16(p02, p03);
            uint32_t h3 = pack_bf16(p12, p13);
            aH[kc * 4 + 0] = h0; aH[kc * 4 + 1] = h1;
            aH[kc * 4 + 2] = h2; aH[kc * 4 + 3] = h3;
            const __nv_bfloat162 b0 = *reinterpret_cast<const __nv_bfloat162*>(&h0);
            const __nv_bfloat162 b1 = *reinterpret_cast<const __nv_bfloat162*>(&h1);
            const __nv_bfloat162 b2 = *reinterpret_cast<const __nv_bfloat162*>(&h2);
            const __nv_bfloat162 b3 = *reinterpret_cast<const __nv_bfloat162*>(&h3);
            aL[kc * 4 + 0] = pack_bf16(p00 - __low2float(b0), p01 - __high2float(b0));
            aL[kc * 4 + 1] = pack_bf16(p10 - __low2float(b1), p11 - __high2float(b1));
            aL[kc * 4 + 2] = pack_bf16(p02 - __low2float(b2), p03 - __high2float(b2));
            aL[kc * 4 + 3] = pack_bf16(p12 - __low2float(b3), p13 - __high2float(b3));
        }

        // ---- Phase B: D += P_hi·H_hi + P_lo·H_hi + P_hi·H_lo (HMMA) ----
#pragma unroll
        for (int nc = 0; nc < 8; nc++) {
            const int n = nc * 8 + g;           // B col (feature)
            const char* rH = hh + n * 144 + qt * 4;
            const char* rL = hl + n * 144 + qt * 4;
#pragma unroll
            for (int kc = 0; kc < 4; kc++) {
                const uint32_t bh0 = *(const uint32_t*)(rH + kc * 32);
                const uint32_t bh1 = *(const uint32_t*)(rH + kc * 32 + 16);
                const uint32_t bl0 = *(const uint32_t*)(rL + kc * 32);
                const uint32_t bl1 = *(const uint32_t*)(rL + kc * 32 + 16);
                mma16816(accs[nc], aH + kc * 4, bh0, bh1);
                mma16816(accs[nc], aL + kc * 4, bh0, bh1);
                mma16816(accs[nc], aH + kc * 4, bl0, bl1);
            }
        }
        __syncthreads();                         // done with buf tt&1
    }

    // ---- store partial l (quad-reduced) and partial D ----
    l0 += __shfl_xor_sync(0xffffffffu, l0, 1);
    l0 += __shfl_xor_sync(0xffffffffu, l0, 2);
    l1 += __shfl_xor_sync(0xffffffffu, l1, 1);
    l1 += __shfl_xor_sync(0xffffffffu, l1, 2);
    if (qt == 0) {
        g_pl[(size_t)js * B_ * N_ + b * N_ + row0 + i0] = l0;
        g_pl[(size_t)js * B_ * N_ + b * N_ + row0 + i1] = l1;
    }

#pragma unroll
    for (int half = 0; half < 2; half++) {
        const int row = row0 + (half ? i1 : i0);
        float* pp = g_pd + (((size_t)js * B_ + b) * N_ + row) * FOUT_;
#pragma unroll
        for (int nc = 0; nc < 8; nc++) {
            const int col = nc * 8 + 2 * qt;
            *(float2*)(pp + col) =
                make_float2(accs[nc][half * 2 + 0], accs[nc][half * 2 + 1]);
        }
    }
}

// ---------------------------------------------------------------------------
// Kernel 3: combine partials -> softmax divide -> LayerNorm -> ELU -> out
// block 256 = 32 rows x 8 threads/row (8 cols each); grid 512.
// ---------------------------------------------------------------------------
__global__ void __launch_bounds__(256)
gat_epilogue_kernel(const float* __restrict__ gamma,
                    const float* __restrict__ beta,
                    float*       __restrict__ out) {
    const int tid   = threadIdx.x;
    const int rloc  = tid >> 3;                   // 0..31
    const int l8    = tid & 7;                    // 0..7
    const int grow  = blockIdx.x * 32 + rloc;     // global row id (b*N+row)

    const size_t base = (size_t)grow * FOUT_ + l8 * 8;
    const float4 d0a = *(const float4*)(g_pd + base);
    const float4 d0b = *(const float4*)(g_pd + base + 4);
    const float4 d1a = *(const float4*)(g_pd + (size_t)B_ * N_ * FOUT_ + base);
    const float4 d1b = *(const float4*)(g_pd + (size_t)B_ * N_ * FOUT_ + base + 4);
    const float  l   = g_pl[grow] + g_pl[B_ * N_ + grow];
    const float  inv = 1.f / l;

    float v[8];
    v[0] = (d0a.x + d1a.x) * inv; v[1] = (d0a.y + d1a.y) * inv;
    v[2] = (d0a.z + d1a.z) * inv; v[3] = (d0a.w + d1a.w) * inv;
    v[4] = (d0b.x + d1b.x) * inv; v[5] = (d0b.y + d1b.y) * inv;
    v[6] = (d0b.z + d1b.z) * inv; v[7] = (d0b.w + d1b.w) * inv;

    float s = 0.f;
#pragma unroll
    for (int c = 0; c < 8; c++) s += v[c];
    s += __shfl_xor_sync(0xffffffffu, s, 1);
    s += __shfl_xor_sync(0xffffffffu, s, 2);
    s += __shfl_xor_sync(0xffffffffu, s, 4);
    const float mu = s * (1.0f / FOUT_);

    float q = 0.f;
#pragma unroll
    for (int c = 0; c < 8; c++) { const float d = v[c] - mu; q += d * d; }
    q += __shfl_xor_sync(0xffffffffu, q, 1);
    q += __shfl_xor_sync(0xffffffffu, q, 2);
    q += __shfl_xor_sync(0xffffffffu, q, 4);
    const float rstd = rsqrtf(q * (1.0f / FOUT_) + 1e-5f);

    const float4 g0 = *(const float4*)(gamma + l8 * 8);
    const float4 g1 = *(const float4*)(gamma + l8 * 8 + 4);
    const float4 b0 = *(const float4*)(beta  + l8 * 8);
    const float4 b1 = *(const float4*)(beta  + l8 * 8 + 4);

    float y[8];
    y[0] = (v[0] - mu) * rstd * g0.x + b0.x;
    y[1] = (v[1] - mu) * rstd * g0.y + b0.y;
    y[2] = (v[2] - mu) * rstd * g0.z + b0.z;
    y[3] = (v[3] - mu) * rstd * g0.w + b0.w;
    y[4] = (v[4] - mu) * rstd * g1.x + b1.x;
    y[5] = (v[5] - mu) * rstd * g1.y + b1.y;
    y[6] = (v[6] - mu) * rstd * g1.z + b1.z;
    y[7] = (v[7] - mu) * rstd * g1.w + b1.w;

    float4 oa, ob;
    oa.x = y[0] > 0.f ? y[0] : expm1f(y[0]);
    oa.y = y[1] > 0.f ? y[1] : expm1f(y[1]);
    oa.z = y[2] > 0.f ? y[2] : expm1f(y[2]);
    oa.w = y[3] > 0.f ? y[3] : expm1f(y[3]);
    ob.x = y[4] > 0.f ? y[4] : expm1f(y[4]);
    ob.y = y[5] > 0.f ? y[5] : expm1f(y[5]);
    ob.z = y[6] > 0.f ? y[6] : expm1f(y[6]);
    ob.w = y[7] > 0.f ? y[7] : expm1f(y[7]);

    *(float4*)(out + base)     = oa;
    *(float4*)(out + base + 4) = ob;
}

// ---------------------------------------------------------------------------
extern "C" void kernel_launch(void* const* d_in, const int* in_sizes, int n_in,
                              void* d_out, int out_size) {
    const float* x     = (const float*)d_in[0];
    const int*   adj   = (const int*)  d_in[1];
    const float* W     = (const float*)d_in[2];
    const float* a     = (const float*)d_in[3];
    const float* gamma = (const float*)d_in[4];
    const float* beta  = (const float*)d_in[5];
    float* out = (float*)d_out;

    cudaFuncSetAttribute(gat_h_kernel,
                         cudaFuncAttributeMaxDynamicSharedMemorySize, 65536);
    cudaFuncSetAttribute(gat_attn_kernel,
                         cudaFuncAttributeMaxDynamicSharedMemorySize, SMEM2);

    gat_h_kernel<<<(B_ * N_) / 64, 256, 65536>>>(x, W, a);
    gat_attn_kernel<<<dim3(N_ / MR, B_, NSPL), 256, SMEM2>>>(adj);
    gat_epilogue_kernel<<<(B_ * N_) / 32, 256>>>(gamma, beta, out);
}